// round 1
// baseline (speedup 1.0000x reference)
#include <cuda_runtime.h>

#define NN 50000
#define EE 800000
#define CC 128
#define SA 132              // padded smem row stride (floats)
#define NTHR 512
#define SMEM_BYTES (3*128*SA*4 + 1024)

// ---------------- scratch (__device__ globals: allocation-free) ----------------
__device__ __align__(16) float g_q[(size_t)NN*CC];
__device__ __align__(16) float g_k[(size_t)NN*CC];
__device__ __align__(16) float g_v[(size_t)NN*CC];
__device__ __align__(16) float g_z[(size_t)NN*CC];
__device__ __align__(16) float g_num[(size_t)NN*CC];
__device__ int g_is64;

// ---------------- packed f32x2 helpers (sm_103a dual-fp32 pipe) ----------------
__device__ __forceinline__ unsigned long long pk2(float lo, float hi){
  unsigned long long r;
  asm("mov.b64 %0, {%1,%2};" : "=l"(r) : "f"(lo), "f"(hi));
  return r;
}
__device__ __forceinline__ float2 up2(unsigned long long v){
  float2 f;
  asm("mov.b64 {%0,%1}, %2;" : "=f"(f.x), "=f"(f.y) : "l"(v));
  return f;
}
__device__ __forceinline__ void fma2(unsigned long long &d, unsigned long long a, unsigned long long b){
  asm("fma.rn.f32x2 %0, %1, %2, %0;" : "+l"(d) : "l"(a), "l"(b));
}

// ---------------- 128x128x128 tile GEMM: C = A * W ----------------
// A: smem [128][SA] row-major (m,k). W: smem [128][SA] (k,n).
// 512 threads: tx=tid&15 (8 cols), ty=tid>>4 (4 rows). acc = 4 rows x 4 col-pairs.
__device__ __forceinline__ void gemm_tile(const float* __restrict__ As,
                                          const float* __restrict__ Ws,
                                          int m0, int n0,
                                          unsigned long long acc[4][4]){
  #pragma unroll
  for (int i=0;i<4;i++)
    #pragma unroll
    for (int j=0;j<4;j++) acc[i][j] = 0ULL;

  #pragma unroll 4
  for (int k=0;k<CC;k++){
    unsigned long long w[4];
    const float* wr = Ws + k*SA + n0;
    #pragma unroll
    for (int j=0;j<4;j++) w[j] = *(const unsigned long long*)(wr + 2*j);
    const float* ar = As + m0*SA + k;
    #pragma unroll
    for (int i=0;i<4;i++){
      float a = ar[i*SA];
      unsigned long long ad = pk2(a, a);
      #pragma unroll
      for (int j=0;j<4;j++) fma2(acc[i][j], ad, w[j]);
    }
  }
}

__device__ __forceinline__ void load_w(float* Ws, const float* __restrict__ W, int tid){
  #pragma unroll
  for (int i = tid; i < 128*32; i += NTHR){
    int k = i >> 5, c4 = i & 31;
    *(float4*)(Ws + k*SA + 4*c4) = *((const float4*)(W + (size_t)k*CC) + c4);
  }
}

__device__ __forceinline__ void epi_relu_smem(unsigned long long acc[4][4],
                                              const float* __restrict__ bias,
                                              float* Bs, int m0, int n0){
  #pragma unroll
  for (int i=0;i<4;i++){
    #pragma unroll
    for (int j=0;j<4;j++){
      float2 p = up2(acc[i][j]);
      float2 o;
      o.x = fmaxf(p.x + bias[n0+2*j],   0.f);
      o.y = fmaxf(p.y + bias[n0+2*j+1], 0.f);
      *(float2*)(Bs + (m0+i)*SA + n0 + 2*j) = o;
    }
  }
}

__device__ __forceinline__ void store_plain(unsigned long long acc[4][4],
                                            float* out, int r0, int m0, int n0){
  #pragma unroll
  for (int i=0;i<4;i++){
    int r = r0 + m0 + i;
    if (r < NN){
      #pragma unroll
      for (int j=0;j<4;j++)
        *(float2*)(out + (size_t)r*CC + n0 + 2*j) = up2(acc[i][j]);
    }
  }
}

// ---------------- detect edge_index element width (int64 vs int32) ----------------
__global__ void detect_kernel(const void* __restrict__ ei){
  const unsigned long long* p = (const unsigned long long*)ei;
  int ok64 = 1;
  for (int i=0;i<64;i++){
    if ((p[i] >> 32) != 0ULL){ ok64 = 0; break; }
  }
  g_is64 = ok64;
}

// ---------------- node kernel: h = relu(xW_in+b); q,k,v = h W_{dst,src,lin} ----------------
__global__ void __launch_bounds__(NTHR,1)
node_qkv_kernel(const float* __restrict__ x,
                const float* __restrict__ W_in, const float* __restrict__ b_in,
                const float* __restrict__ W_dst, const float* __restrict__ W_src,
                const float* __restrict__ W_lin){
  extern __shared__ float sm[];
  float* As = sm;
  float* Bs = sm + 128*SA;
  float* Ws = sm + 2*128*SA;
  int tid = threadIdx.x;
  int tx = tid & 15, ty = tid >> 4;
  int m0 = ty*4, n0 = tx*8;
  int r0 = blockIdx.x * 128;

  load_w(Ws, W_in, tid);
  #pragma unroll 1
  for (int i = tid; i < 128*32; i += NTHR){
    int r = i >> 5, c4 = i & 31;
    float4 v = make_float4(0.f,0.f,0.f,0.f);
    if (r0 + r < NN) v = *((const float4*)(x + (size_t)(r0+r)*CC) + c4);
    *(float4*)(As + r*SA + 4*c4) = v;
  }
  __syncthreads();

  unsigned long long acc[4][4];
  gemm_tile(As, Ws, m0, n0, acc);
  __syncthreads();
  epi_relu_smem(acc, b_in, Bs, m0, n0);
  load_w(Ws, W_dst, tid);
  __syncthreads();

  gemm_tile(Bs, Ws, m0, n0, acc);
  store_plain(acc, g_q, r0, m0, n0);
  __syncthreads();
  load_w(Ws, W_src, tid);
  __syncthreads();

  gemm_tile(Bs, Ws, m0, n0, acc);
  store_plain(acc, g_k, r0, m0, n0);
  __syncthreads();
  load_w(Ws, W_lin, tid);
  __syncthreads();

  gemm_tile(Bs, Ws, m0, n0, acc);
  store_plain(acc, g_v, r0, m0, n0);
}

// ---------------- edge kernel: delta MLP, attn MLP, exp, fused numerator+z reduction ----------------
__global__ void __launch_bounds__(NTHR,1)
edge_kernel(const float* __restrict__ pos, const void* __restrict__ ei,
            const float* __restrict__ pw1, const float* __restrict__ pb1,
            const float* __restrict__ pw2, const float* __restrict__ pb2,
            const float* __restrict__ aw1, const float* __restrict__ ab1,
            const float* __restrict__ aw2, const float* __restrict__ ab2){
  extern __shared__ float sm[];
  float* As = sm;
  float* Bs = sm + 128*SA;
  float* Ws = sm + 2*128*SA;
  int* si = (int*)(sm + 3*128*SA);
  int* di = si + 128;
  int tid = threadIdx.x;
  int tx = tid & 15, ty = tid >> 4;
  int m0 = ty*4, n0 = tx*8;
  long long e0 = (long long)blockIdx.x * 128;

  if (tid < 128){
    if (g_is64){
      const long long* p = (const long long*)ei;
      si[tid] = (int)p[e0 + tid];
      di[tid] = (int)p[(long long)EE + e0 + tid];
    } else {
      const int* p = (const int*)ei;
      si[tid] = p[e0 + tid];
      di[tid] = p[(long long)EE + e0 + tid];
    }
  }
  load_w(Ws, pw1, tid);
  __syncthreads();

  // pd = pos[dst] - pos[src] -> As (row gathers are coalesced, pos is L2-resident)
  #pragma unroll 1
  for (int i = tid; i < 128*32; i += NTHR){
    int e = i >> 5, c4 = i & 31;
    float4 a = *((const float4*)(pos + (size_t)di[e]*CC) + c4);
    float4 b = *((const float4*)(pos + (size_t)si[e]*CC) + c4);
    *(float4*)(As + e*SA + 4*c4) = make_float4(a.x-b.x, a.y-b.y, a.z-b.z, a.w-b.w);
  }
  __syncthreads();

  unsigned long long acc[4][4];
  // pos_nn layer 1
  gemm_tile(As, Ws, m0, n0, acc);
  __syncthreads();
  epi_relu_smem(acc, pb1, Bs, m0, n0);
  load_w(Ws, pw2, tid);
  __syncthreads();

  // pos_nn layer 2 -> delta kept in registers
  gemm_tile(Bs, Ws, m0, n0, acc);
  float2 dlt[4][4];
  #pragma unroll
  for (int i=0;i<4;i++)
    #pragma unroll
    for (int j=0;j<4;j++){
      float2 p = up2(acc[i][j]);
      dlt[i][j].x = fmaxf(p.x + pb2[n0+2*j],   0.f);
      dlt[i][j].y = fmaxf(p.y + pb2[n0+2*j+1], 0.f);
    }
  __syncthreads();

  // attn input = q[dst] - k[src] + delta -> As
  #pragma unroll
  for (int i=0;i<4;i++){
    int m = m0 + i;
    const float* qr = g_q + (size_t)di[m]*CC + n0;
    const float* kr = g_k + (size_t)si[m]*CC + n0;
    #pragma unroll
    for (int j=0;j<4;j++){
      float2 qv = *(const float2*)(qr + 2*j);
      float2 kv = *(const float2*)(kr + 2*j);
      float2 o;
      o.x = qv.x - kv.x + dlt[i][j].x;
      o.y = qv.y - kv.y + dlt[i][j].y;
      *(float2*)(As + m*SA + n0 + 2*j) = o;
    }
  }
  load_w(Ws, aw1, tid);
  __syncthreads();

  // attn_nn layer 1
  gemm_tile(As, Ws, m0, n0, acc);
  __syncthreads();
  epi_relu_smem(acc, ab1, Bs, m0, n0);
  load_w(Ws, aw2, tid);
  __syncthreads();

  // attn_nn layer 2 -> alpha -> ea = exp(alpha); numerator p = ea*(v[src]+delta)
  gemm_tile(Bs, Ws, m0, n0, acc);

  #pragma unroll
  for (int i=0;i<4;i++){
    int m = m0 + i;
    const float* vr = g_v + (size_t)si[m]*CC + n0;
    float ea[8], pp[8];
    #pragma unroll
    for (int j=0;j<4;j++){
      float2 a2 = up2(acc[i][j]);
      float al0 = fmaxf(a2.x + ab2[n0+2*j],   0.f);
      float al1 = fmaxf(a2.y + ab2[n0+2*j+1], 0.f);
      // alpha >= 0 and small: softmax without max-subtraction is exact here
      float e0f = __expf(al0), e1f = __expf(al1);
      float2 vv = *(const float2*)(vr + 2*j);
      ea[2*j]   = e0f;  ea[2*j+1]   = e1f;
      pp[2*j]   = e0f * (vv.x + dlt[i][j].x);
      pp[2*j+1] = e1f * (vv.y + dlt[i][j].y);
    }
    float* zp = g_z   + (size_t)di[m]*CC + n0;
    float* np = g_num + (size_t)di[m]*CC + n0;
    asm volatile("red.global.add.v4.f32 [%0], {%1,%2,%3,%4};"
                 :: "l"(zp),   "f"(ea[0]),"f"(ea[1]),"f"(ea[2]),"f"(ea[3]) : "memory");
    asm volatile("red.global.add.v4.f32 [%0], {%1,%2,%3,%4};"
                 :: "l"(zp+4), "f"(ea[4]),"f"(ea[5]),"f"(ea[6]),"f"(ea[7]) : "memory");
    asm volatile("red.global.add.v4.f32 [%0], {%1,%2,%3,%4};"
                 :: "l"(np),   "f"(pp[0]),"f"(pp[1]),"f"(pp[2]),"f"(pp[3]) : "memory");
    asm volatile("red.global.add.v4.f32 [%0], {%1,%2,%3,%4};"
                 :: "l"(np+4), "f"(pp[4]),"f"(pp[5]),"f"(pp[6]),"f"(pp[7]) : "memory");
  }
}

// ---------------- output kernel: agg = num/z ; out = relu(agg W_out + b_out) ----------------
__global__ void __launch_bounds__(NTHR,1)
out_kernel(const float* __restrict__ W_out, const float* __restrict__ b_out,
           float* __restrict__ out){
  extern __shared__ float sm[];
  float* As = sm;
  float* Ws = sm + 2*128*SA;
  int tid = threadIdx.x;
  int tx = tid & 15, ty = tid >> 4;
  int m0 = ty*4, n0 = tx*8;
  int r0 = blockIdx.x * 128;

  load_w(Ws, W_out, tid);
  #pragma unroll 1
  for (int i = tid; i < 128*32; i += NTHR){
    int r = i >> 5, c4 = i & 31;
    float4 a = make_float4(0.f,0.f,0.f,0.f);
    if (r0 + r < NN){
      float4 nm = *((const float4*)(g_num + (size_t)(r0+r)*CC) + c4);
      float4 zz = *((const float4*)(g_z   + (size_t)(r0+r)*CC) + c4);
      a.x = nm.x / (zz.x + 1e-16f);
      a.y = nm.y / (zz.y + 1e-16f);
      a.z = nm.z / (zz.z + 1e-16f);
      a.w = nm.w / (zz.w + 1e-16f);
    }
    *(float4*)(As + r*SA + 4*c4) = a;
  }
  __syncthreads();

  unsigned long long acc[4][4];
  gemm_tile(As, Ws, m0, n0, acc);

  #pragma unroll
  for (int i=0;i<4;i++){
    int r = r0 + m0 + i;
    if (r < NN){
      #pragma unroll
      for (int j=0;j<4;j++){
        float2 p = up2(acc[i][j]);
        float2 o;
        o.x = fmaxf(p.x + b_out[n0+2*j],   0.f);
        o.y = fmaxf(p.y + b_out[n0+2*j+1], 0.f);
        *(float2*)(out + (size_t)r*CC + n0 + 2*j) = o;
      }
    }
  }
}

// ---------------- launch ----------------
extern "C" void kernel_launch(void* const* d_in, const int* in_sizes, int n_in,
                              void* d_out, int out_size){
  const float* x    = (const float*)d_in[0];
  const float* pos  = (const float*)d_in[1];
  const void*  ei   = d_in[2];
  const float* W_in = (const float*)d_in[3];
  const float* b_in = (const float*)d_in[4];
  const float* W_lin= (const float*)d_in[5];
  const float* W_src= (const float*)d_in[6];
  const float* W_dst= (const float*)d_in[7];
  const float* pw1  = (const float*)d_in[8];
  const float* pb1  = (const float*)d_in[9];
  const float* pw2  = (const float*)d_in[10];
  const float* pb2  = (const float*)d_in[11];
  const float* aw1  = (const float*)d_in[12];
  const float* ab1  = (const float*)d_in[13];
  const float* aw2  = (const float*)d_in[14];
  const float* ab2  = (const float*)d_in[15];
  const float* W_out= (const float*)d_in[16];
  const float* b_out= (const float*)d_in[17];

  cudaFuncSetAttribute(node_qkv_kernel, cudaFuncAttributeMaxDynamicSharedMemorySize, SMEM_BYTES);
  cudaFuncSetAttribute(edge_kernel,     cudaFuncAttributeMaxDynamicSharedMemorySize, SMEM_BYTES);
  cudaFuncSetAttribute(out_kernel,      cudaFuncAttributeMaxDynamicSharedMemorySize, SMEM_BYTES);

  void *zp = nullptr, *np = nullptr;
  cudaGetSymbolAddress(&zp, g_z);
  cudaGetSymbolAddress(&np, g_num);
  cudaMemsetAsync(zp, 0, (size_t)NN*CC*sizeof(float), 0);
  cudaMemsetAsync(np, 0, (size_t)NN*CC*sizeof(float), 0);

  detect_kernel<<<1, 1>>>(ei);
  node_qkv_kernel<<<(NN+127)/128, NTHR, SMEM_BYTES>>>(x, W_in, b_in, W_dst, W_src, W_lin);
  edge_kernel<<<EE/128, NTHR, SMEM_BYTES>>>(pos, ei, pw1, pb1, pw2, pb2, aw1, ab1, aw2, ab2);
  out_kernel<<<(NN+127)/128, NTHR, SMEM_BYTES>>>(W_out, b_out, (float*)d_out);
}